// round 7
// baseline (speedup 1.0000x reference)
#include <cuda_runtime.h>
#include <cuda_bf16.h>

// ESN: T=2048 steps, N=2048 reservoir, D=128 input.
// out[t] = erf(U[t] + W_res @ out[t-1]) * 1/sqrt(N),  U = input @ W_in^T
#define T_STEPS 2048
#define N_RES   2048
#define D_IN    128
#define GBLK    128          // persistent blocks (1 per SM, all co-resident)
#define ROWS_PER_BLK 16      // N_RES / GBLK
#define NTHREADS 256
#define CPT      8           // columns per thread = N_RES / NTHREADS
#define NPAIR    8           // row pairs per block (f32x2 packs 2 rows)
#define INV_SQRT_N 0.022097086912079612f

__device__ float    g_U[T_STEPS * N_RES];   // input projection scratch (16 MB)
__device__ unsigned g_flag[GBLK];           // per-block monotonic step flags
__device__ unsigned g_count;                // init-barrier arrive counter
__device__ unsigned g_epoch;                // init-barrier epoch (monotonic across runs)

typedef unsigned long long u64;

__device__ __forceinline__ u64 pack2(float lo, float hi) {
    u64 r; asm("mov.b64 %0, {%1,%2};" : "=l"(r) : "f"(lo), "f"(hi)); return r;
}
__device__ __forceinline__ void unpack2(u64 v, float& lo, float& hi) {
    asm("mov.b64 {%0,%1}, %2;" : "=f"(lo), "=f"(hi) : "l"(v));
}
__device__ __forceinline__ void fma2(u64& acc, u64 a, u64 b) {
    asm("fma.rn.f32x2 %0, %1, %2, %0;" : "+l"(acc) : "l"(a), "l"(b));
}
__device__ __forceinline__ u64 add2(u64 a, u64 b) {
    u64 r; asm("add.rn.f32x2 %0, %1, %2;" : "=l"(r) : "l"(a), "l"(b)); return r;
}
__device__ __forceinline__ u64 shfl_xor64(u64 v, int m) {
    unsigned lo = (unsigned)v, hi = (unsigned)(v >> 32);
    lo = __shfl_xor_sync(0xffffffffu, lo, m);
    hi = __shfl_xor_sync(0xffffffffu, hi, m);
    return ((u64)hi << 32) | (u64)lo;
}

// One-time grid barrier at kernel start (epoch agreement only) — proven in R3.
__device__ __forceinline__ void grid_barrier(int tid, unsigned target) {
    __syncthreads();
    if (tid == 0) {
        unsigned prev;
        asm volatile("atom.release.gpu.global.add.u32 %0, [%1], %2;"
                     : "=r"(prev) : "l"(&g_count), "r"(1u) : "memory");
        if (prev == (unsigned)(GBLK - 1)) {
            asm volatile("st.relaxed.gpu.global.u32 [%0], %1;"
                         :: "l"(&g_count), "r"(0u) : "memory");
            asm volatile("st.release.gpu.global.u32 [%0], %1;"
                         :: "l"(&g_epoch), "r"(target) : "memory");
        } else {
            unsigned cur;
            do {
                asm volatile("ld.acquire.gpu.global.u32 %0, [%1];"
                             : "=r"(cur) : "l"(&g_epoch) : "memory");
            } while (cur != target);
        }
    }
    __syncthreads();
}

// Wrap-safe acquire-poll on a producer block's monotonic flag.
__device__ __forceinline__ void wait_flag(const unsigned* f, unsigned target) {
    unsigned cur;
    do {
        asm volatile("ld.acquire.gpu.global.u32 %0, [%1];"
                     : "=r"(cur) : "l"(f) : "memory");
    } while ((int)(cur - target) < 0);
}

// ---------------------------------------------------------------------------
// Kernel 1: U[t][n] = sum_d input[t][d] * W_in[n][d]   (2048 x 2048 x 128)
// ---------------------------------------------------------------------------
__global__ void __launch_bounds__(256) u_gemm_kernel(
    const float* __restrict__ inp, const float* __restrict__ win)
{
    __shared__ float As[32][129];
    __shared__ float Bs[32][129];
    const int tid = threadIdx.x;
    const int t0 = blockIdx.y * 32;
    const int n0 = blockIdx.x * 32;

    #pragma unroll
    for (int i = 0; i < 4; i++) {
        int f   = tid + i * 256;
        int row = f >> 5;
        int c4  = (f & 31) << 2;
        float4 va = *(const float4*)(inp + (t0 + row) * D_IN + c4);
        float4 vb = *(const float4*)(win + (n0 + row) * D_IN + c4);
        As[row][c4] = va.x; As[row][c4 + 1] = va.y; As[row][c4 + 2] = va.z; As[row][c4 + 3] = va.w;
        Bs[row][c4] = vb.x; Bs[row][c4 + 1] = vb.y; Bs[row][c4 + 2] = vb.z; Bs[row][c4 + 3] = vb.w;
    }
    __syncthreads();

    const int tx = tid & 15, ty = tid >> 4;
    float a00 = 0.f, a01 = 0.f, a10 = 0.f, a11 = 0.f;
    #pragma unroll 16
    for (int k = 0; k < D_IN; k++) {
        float x0 = As[2 * ty][k],     x1 = As[2 * ty + 1][k];
        float y0 = Bs[2 * tx][k],     y1 = Bs[2 * tx + 1][k];
        a00 = fmaf(x0, y0, a00); a01 = fmaf(x0, y1, a01);
        a10 = fmaf(x1, y0, a10); a11 = fmaf(x1, y1, a11);
    }
    const int r = t0 + 2 * ty, c = n0 + 2 * tx;
    g_U[r * N_RES + c]           = a00;
    g_U[r * N_RES + c + 1]       = a01;
    g_U[(r + 1) * N_RES + c]     = a10;
    g_U[(r + 1) * N_RES + c + 1] = a11;
}

// ---------------------------------------------------------------------------
// Kernel 2: persistent recurrence == R3's proven kernel, with the central
// per-step barrier replaced by decentralized per-block flags carrying R3's
// exact ordering discipline:
//   producer: out stores -> threadfence -> bar.sync -> st.release flag
//   consumer: ld.acquire flag poll -> ldcg out reads
// Consumer thread tid depends on exactly ONE producer block (tid/2): it
// proceeds the moment that block finishes; out rows are never reused so
// there is no buffer-overwrite hazard of any kind.
// ---------------------------------------------------------------------------
__global__ void __launch_bounds__(NTHREADS, 1) esn_recur_kernel(
    const float* __restrict__ wres, float* __restrict__ out)
{
    __shared__ u64 red[NPAIR * NTHREADS];   // 16 KB reduction staging

    const int tid = threadIdx.x;
    const int bid = blockIdx.x;
    const int r0  = bid * ROWS_PER_BLK;
    const int c0  = tid * CPT;
    const int wp  = tid >> 5, ln = tid & 31;
    const int fj  = tid >> 1;               // my producer block (owns cols c0..c0+7)

    // Load W_res slice: w[p][c] = {W[r0+2p][c0+c], W[r0+2p+1][c0+c]}
    u64 w[NPAIR][CPT];
    #pragma unroll
    for (int p = 0; p < NPAIR; p++) {
        const float4* ra = (const float4*)(wres + (r0 + 2 * p)     * N_RES + c0);
        const float4* rb = (const float4*)(wres + (r0 + 2 * p + 1) * N_RES + c0);
        float4 a0 = ra[0], a1 = ra[1];
        float4 b0 = rb[0], b1 = rb[1];
        w[p][0] = pack2(a0.x, b0.x); w[p][1] = pack2(a0.y, b0.y);
        w[p][2] = pack2(a0.z, b0.z); w[p][3] = pack2(a0.w, b0.w);
        w[p][4] = pack2(a1.x, b1.x); w[p][5] = pack2(a1.y, b1.y);
        w[p][6] = pack2(a1.z, b1.z); w[p][7] = pack2(a1.w, b1.w);
    }

    // Epoch agreement (one-time): all blocks read identical e0 pre-arrival.
    unsigned e0;
    asm volatile("ld.acquire.gpu.global.u32 %0, [%1];" : "=r"(e0) : "l"(&g_epoch) : "memory");
    grid_barrier(tid, e0 + 1);
    const unsigned base = (e0 + 1) << 12;   // > any flag value from previous runs

    // Step 0: x0 = erf(U[0]) * inv_sqrt_n
    if (tid < ROWS_PER_BLK) {
        out[r0 + tid] = erff(g_U[r0 + tid]) * INV_SQRT_N;
        __threadfence();
    }
    __syncthreads();
    if (tid == 0)
        asm volatile("st.release.gpu.global.u32 [%0], %1;"
                     :: "l"(&g_flag[bid]), "r"(base) : "memory");

    #pragma unroll 1
    for (int t = 1; t < T_STEPS; t++) {
        // Prefetch U[t] for my rows (lane 0 of each warp) before waiting.
        float u0 = 0.f, u1 = 0.f;
        if (ln == 0) {
            u0 = __ldg(&g_U[t * N_RES + r0 + 2 * wp]);
            u1 = __ldg(&g_U[t * N_RES + r0 + 2 * wp + 1]);
        }

        // Wait for MY producer block only.
        wait_flag(&g_flag[fj], base + (unsigned)(t - 1));

        // Load my 8 x values from the previous out row (L1 bypass: remote SMs).
        const float4* xp = (const float4*)(out + (t - 1) * N_RES + c0);
        float4 xv0 = __ldcg(xp);
        float4 xv1 = __ldcg(xp + 1);
        u64 xx[CPT];
        xx[0] = pack2(xv0.x, xv0.x); xx[1] = pack2(xv0.y, xv0.y);
        xx[2] = pack2(xv0.z, xv0.z); xx[3] = pack2(xv0.w, xv0.w);
        xx[4] = pack2(xv1.x, xv1.x); xx[5] = pack2(xv1.y, xv1.y);
        xx[6] = pack2(xv1.z, xv1.z); xx[7] = pack2(xv1.w, xv1.w);

        u64 acc[NPAIR];
        #pragma unroll
        for (int p = 0; p < NPAIR; p++) acc[p] = 0ULL;
        #pragma unroll
        for (int c = 0; c < CPT; c++) {
            #pragma unroll
            for (int p = 0; p < NPAIR; p++) fma2(acc[p], w[p][c], xx[c]);
        }

        // Stage partials; warp wp reduces row-pair wp across 256 threads.
        #pragma unroll
        for (int p = 0; p < NPAIR; p++) red[p * NTHREADS + tid] = acc[p];
        __syncthreads();

        u64 s = red[wp * NTHREADS + ln];
        #pragma unroll
        for (int k = 1; k < 8; k++) s = add2(s, red[wp * NTHREADS + ln + 32 * k]);
        #pragma unroll
        for (int m = 16; m >= 1; m >>= 1) s = add2(s, shfl_xor64(s, m));

        if (ln == 0) {
            float lo, hi; unpack2(s, lo, hi);
            const int r = r0 + 2 * wp;
            out[t * N_RES + r]     = erff(u0 + lo) * INV_SQRT_N;
            out[t * N_RES + r + 1] = erff(u1 + hi) * INV_SQRT_N;
            __threadfence();
        }
        __syncthreads();   // all out stores done + red[] safe for reuse

        if (tid == 0)
            asm volatile("st.release.gpu.global.u32 [%0], %1;"
                         :: "l"(&g_flag[bid]), "r"(base + (unsigned)t) : "memory");
    }
}

// ---------------------------------------------------------------------------
extern "C" void kernel_launch(void* const* d_in, const int* in_sizes, int n_in,
                              void* d_out, int out_size)
{
    const float* input = (const float*)d_in[0];   // (2048, 128)
    const float* w_in  = (const float*)d_in[1];   // (2048, 128)
    const float* w_res = (const float*)d_in[2];   // (2048, 2048)
    float* out = (float*)d_out;                   // (2048, 2048)

    u_gemm_kernel<<<dim3(N_RES / 32, T_STEPS / 32), 256>>>(input, w_in);
    esn_recur_kernel<<<GBLK, NTHREADS>>>(w_res, out);
}

// round 8
// speedup vs baseline: 4.3194x; 4.3194x over previous
#include <cuda_runtime.h>
#include <cuda_bf16.h>

// ESN: T=2048 steps, N=2048 reservoir, D=128 input.
// out[t] = erf(U[t] + W_res @ out[t-1]) * 1/sqrt(N),  U = input @ W_in^T
#define T_STEPS 2048
#define N_RES   2048
#define D_IN    128
#define GBLK    128          // persistent blocks (1 per SM, all co-resident)
#define ROWS_PER_BLK 16      // N_RES / GBLK
#define NTHREADS 256
#define CPT      8           // columns per thread = N_RES / NTHREADS
#define NPAIR    8           // row pairs per block (f32x2 packs 2 rows)
#define INV_SQRT_N 0.022097086912079612f

__device__ float    g_U[T_STEPS * N_RES];   // input projection scratch (16 MB)
__device__ unsigned g_scount;               // accumulating step counter (never reset)
__device__ unsigned g_count;                // init-barrier arrive counter
__device__ unsigned g_epoch;                // init-barrier epoch (monotonic across runs)

typedef unsigned long long u64;

__device__ __forceinline__ u64 pack2(float lo, float hi) {
    u64 r; asm("mov.b64 %0, {%1,%2};" : "=l"(r) : "f"(lo), "f"(hi)); return r;
}
__device__ __forceinline__ void unpack2(u64 v, float& lo, float& hi) {
    asm("mov.b64 {%0,%1}, %2;" : "=f"(lo), "=f"(hi) : "l"(v));
}
__device__ __forceinline__ void fma2(u64& acc, u64 a, u64 b) {
    asm("fma.rn.f32x2 %0, %1, %2, %0;" : "+l"(acc) : "l"(a), "l"(b));
}
__device__ __forceinline__ u64 add2(u64 a, u64 b) {
    u64 r; asm("add.rn.f32x2 %0, %1, %2;" : "=l"(r) : "l"(a), "l"(b)); return r;
}
__device__ __forceinline__ u64 shfl_xor64(u64 v, int m) {
    unsigned lo = (unsigned)v, hi = (unsigned)(v >> 32);
    lo = __shfl_xor_sync(0xffffffffu, lo, m);
    hi = __shfl_xor_sync(0xffffffffu, hi, m);
    return ((u64)hi << 32) | (u64)lo;
}

// One-time grid barrier at kernel start (epoch + counter-base agreement).
__device__ __forceinline__ void grid_barrier(int tid, unsigned target) {
    __syncthreads();
    if (tid == 0) {
        unsigned prev;
        asm volatile("atom.release.gpu.global.add.u32 %0, [%1], %2;"
                     : "=r"(prev) : "l"(&g_count), "r"(1u) : "memory");
        if (prev == (unsigned)(GBLK - 1)) {
            asm volatile("st.relaxed.gpu.global.u32 [%0], %1;"
                         :: "l"(&g_count), "r"(0u) : "memory");
            asm volatile("st.release.gpu.global.u32 [%0], %1;"
                         :: "l"(&g_epoch), "r"(target) : "memory");
        } else {
            unsigned cur;
            do {
                asm volatile("ld.acquire.gpu.global.u32 %0, [%1];"
                             : "=r"(cur) : "l"(&g_epoch) : "memory");
            } while (cur != target);
        }
    }
    __syncthreads();
}

// ---------------------------------------------------------------------------
// Kernel 1: U[t][n] = sum_d input[t][d] * W_in[n][d]   (2048 x 2048 x 128)
// ---------------------------------------------------------------------------
__global__ void __launch_bounds__(256) u_gemm_kernel(
    const float* __restrict__ inp, const float* __restrict__ win)
{
    __shared__ float As[32][129];
    __shared__ float Bs[32][129];
    const int tid = threadIdx.x;
    const int t0 = blockIdx.y * 32;
    const int n0 = blockIdx.x * 32;

    #pragma unroll
    for (int i = 0; i < 4; i++) {
        int f   = tid + i * 256;
        int row = f >> 5;
        int c4  = (f & 31) << 2;
        float4 va = *(const float4*)(inp + (t0 + row) * D_IN + c4);
        float4 vb = *(const float4*)(win + (n0 + row) * D_IN + c4);
        As[row][c4] = va.x; As[row][c4 + 1] = va.y; As[row][c4 + 2] = va.z; As[row][c4 + 3] = va.w;
        Bs[row][c4] = vb.x; Bs[row][c4 + 1] = vb.y; Bs[row][c4 + 2] = vb.z; Bs[row][c4 + 3] = vb.w;
    }
    __syncthreads();

    const int tx = tid & 15, ty = tid >> 4;
    float a00 = 0.f, a01 = 0.f, a10 = 0.f, a11 = 0.f;
    #pragma unroll 16
    for (int k = 0; k < D_IN; k++) {
        float x0 = As[2 * ty][k],     x1 = As[2 * ty + 1][k];
        float y0 = Bs[2 * tx][k],     y1 = Bs[2 * tx + 1][k];
        a00 = fmaf(x0, y0, a00); a01 = fmaf(x0, y1, a01);
        a10 = fmaf(x1, y0, a10); a11 = fmaf(x1, y1, a11);
    }
    const int r = t0 + 2 * ty, c = n0 + 2 * tx;
    g_U[r * N_RES + c]           = a00;
    g_U[r * N_RES + c + 1]       = a01;
    g_U[(r + 1) * N_RES + c]     = a10;
    g_U[(r + 1) * N_RES + c + 1] = a11;
}

// ---------------------------------------------------------------------------
// Kernel 2: persistent recurrence, R3 topology (1 poller/block) with a
// single-hop counting barrier:
//   producer: out stores -> bar.sync -> tid0 red.release.gpu.add(counter)
//   consumer: tid0 ld.acquire-polls counter >= cbase + 128*t -> bar.sync
// No per-step threadfence; no epoch re-broadcast hop; only 128 pollers
// chip-wide (R7 showed 32K pollers melt the LTS).
// ---------------------------------------------------------------------------
__global__ void __launch_bounds__(NTHREADS, 1) esn_recur_kernel(
    const float* __restrict__ wres, float* __restrict__ out)
{
    __shared__ u64 red[NPAIR * NTHREADS];   // 16 KB reduction staging
    __shared__ unsigned s_cbase;

    const int tid = threadIdx.x;
    const int bid = blockIdx.x;
    const int r0  = bid * ROWS_PER_BLK;
    const int c0  = tid * CPT;
    const int wp  = tid >> 5, ln = tid & 31;

    // Load W_res slice: w[p][c] = {W[r0+2p][c0+c], W[r0+2p+1][c0+c]}
    u64 w[NPAIR][CPT];
    #pragma unroll
    for (int p = 0; p < NPAIR; p++) {
        const float4* ra = (const float4*)(wres + (r0 + 2 * p)     * N_RES + c0);
        const float4* rb = (const float4*)(wres + (r0 + 2 * p + 1) * N_RES + c0);
        float4 a0 = ra[0], a1 = ra[1];
        float4 b0 = rb[0], b1 = rb[1];
        w[p][0] = pack2(a0.x, b0.x); w[p][1] = pack2(a0.y, b0.y);
        w[p][2] = pack2(a0.z, b0.z); w[p][3] = pack2(a0.w, b0.w);
        w[p][4] = pack2(a1.x, b1.x); w[p][5] = pack2(a1.y, b1.y);
        w[p][6] = pack2(a1.z, b1.z); w[p][7] = pack2(a1.w, b1.w);
    }

    // Snapshot the quiescent step-counter, then init barrier so no block can
    // arrive (red.add) before every block has snapshotted the same value.
    if (tid == 0) {
        unsigned c;
        asm volatile("ld.relaxed.gpu.global.u32 %0, [%1];" : "=r"(c) : "l"(&g_scount) : "memory");
        s_cbase = c;
    }
    unsigned e0;
    asm volatile("ld.acquire.gpu.global.u32 %0, [%1];" : "=r"(e0) : "l"(&g_epoch) : "memory");
    grid_barrier(tid, e0 + 1);
    const unsigned cbase = s_cbase;

    // Step 0: x0 = erf(U[0]) * inv_sqrt_n ; then arrive.
    if (tid < ROWS_PER_BLK)
        out[r0 + tid] = erff(g_U[r0 + tid]) * INV_SQRT_N;
    __syncthreads();   // out stores happen-before tid0's release-arrival
    if (tid == 0)
        asm volatile("red.release.gpu.global.add.u32 [%0], %1;"
                     :: "l"(&g_scount), "r"(1u) : "memory");

    #pragma unroll 1
    for (int t = 1; t < T_STEPS; t++) {
        // Prefetch U[t] for my row (lanes 0/1 of each warp) before the wait.
        float u = 0.f;
        if (ln < 2) u = __ldg(&g_U[t * N_RES + r0 + 2 * wp + ln]);

        // Single-hop barrier wait: counter reaches GBLK*t when all blocks
        // have published step t-1. Wrap-safe compare; counter never reset.
        if (tid == 0) {
            const unsigned tgt = cbase + (unsigned)(GBLK * t);
            unsigned cur;
            do {
                asm volatile("ld.acquire.gpu.global.u32 %0, [%1];"
                             : "=r"(cur) : "l"(&g_scount) : "memory");
            } while ((int)(cur - tgt) < 0);
        }
        __syncthreads();   // broadcast: acquire happens-before all lanes' loads

        // Load my 8 x values from the previous out row (L1 bypass: remote SMs).
        const float4* xp = (const float4*)(out + (t - 1) * N_RES + c0);
        float4 xv0 = __ldcg(xp);
        float4 xv1 = __ldcg(xp + 1);
        u64 xx[CPT];
        xx[0] = pack2(xv0.x, xv0.x); xx[1] = pack2(xv0.y, xv0.y);
        xx[2] = pack2(xv0.z, xv0.z); xx[3] = pack2(xv0.w, xv0.w);
        xx[4] = pack2(xv1.x, xv1.x); xx[5] = pack2(xv1.y, xv1.y);
        xx[6] = pack2(xv1.z, xv1.z); xx[7] = pack2(xv1.w, xv1.w);

        u64 acc[NPAIR];
        #pragma unroll
        for (int p = 0; p < NPAIR; p++) acc[p] = 0ULL;
        #pragma unroll
        for (int c = 0; c < CPT; c++) {
            #pragma unroll
            for (int p = 0; p < NPAIR; p++) fma2(acc[p], w[p][c], xx[c]);
        }

        // Stage partials; warp wp reduces row-pair wp across 256 threads.
        #pragma unroll
        for (int p = 0; p < NPAIR; p++) red[p * NTHREADS + tid] = acc[p];
        __syncthreads();

        u64 s = red[wp * NTHREADS + ln];
        #pragma unroll
        for (int k = 1; k < 8; k++) s = add2(s, red[wp * NTHREADS + ln + 32 * k]);
        #pragma unroll
        for (int m = 16; m >= 1; m >>= 1) s = add2(s, shfl_xor64(s, m));
        // Every lane now holds the full {row 2wp, row 2wp+1} dot-product pair.

        // Lanes 0/1 each finish one row: erf + out store (parallel erfs).
        if (ln < 2) {
            float lo, hi; unpack2(s, lo, hi);
            float pre = u + (ln == 0 ? lo : hi);
            out[t * N_RES + r0 + 2 * wp + ln] = erff(pre) * INV_SQRT_N;
        }
        __syncthreads();   // out stores done + red[] safe; HB to tid0 arrival

        if (tid == 0)
            asm volatile("red.release.gpu.global.add.u32 [%0], %1;"
                         :: "l"(&g_scount), "r"(1u) : "memory");
    }
}

// ---------------------------------------------------------------------------
extern "C" void kernel_launch(void* const* d_in, const int* in_sizes, int n_in,
                              void* d_out, int out_size)
{
    const float* input = (const float*)d_in[0];   // (2048, 128)
    const float* w_in  = (const float*)d_in[1];   // (2048, 128)
    const float* w_res = (const float*)d_in[2];   // (2048, 2048)
    float* out = (float*)d_out;                   // (2048, 2048)

    u_gemm_kernel<<<dim3(N_RES / 32, T_STEPS / 32), 256>>>(input, w_in);
    esn_recur_kernel<<<GBLK, NTHREADS>>>(w_res, out);
}